// round 4
// baseline (speedup 1.0000x reference)
#include <cuda_runtime.h>

#define NN 50000
#define EE 800000
#define DD 128
#define NV4 32          // DD/4
#define LN_EPS 1e-5f

// ---------------- device scratch (static globals; no allocation) -------------
static __device__ int    g_cnt_in[NN];
static __device__ int    g_cnt_out[NN];
static __device__ int    g_row_ptr[NN + 1];
static __device__ int    g_cursor[NN];
static __device__ int    g_col[EE];
static __device__ int    g_blk[128];
static __device__ float  g_iso[NN];
static __device__ float  g_isi[NN];
static __device__ float4 g_hs [NN * NV4];
static __device__ float4 g_agg[NN * NV4];
static __device__ float4 g_h1 [NN * NV4];

__device__ __forceinline__ int clamp_idx(int v, int n) {
    // defensive: keep any unexpected value in-range (wrong answer > wild fault)
    unsigned u = (unsigned)v;
    return (u < (unsigned)n) ? v : 0;
}

// ---------------- graph prep -------------------------------------------------
__global__ void k_zero(int n) {
    int i = blockIdx.x * blockDim.x + threadIdx.x;
    if (i < n) { g_cnt_in[i] = 0; g_cnt_out[i] = 0; g_cursor[i] = 0; }
}

__global__ void k_degree(const int* __restrict__ src,
                         const int* __restrict__ dst, int e, int n) {
    int i = blockIdx.x * blockDim.x + threadIdx.x;
    if (i < e) {
        atomicAdd(&g_cnt_out[clamp_idx(src[i], n)], 1);
        atomicAdd(&g_cnt_in [clamp_idx(dst[i], n)], 1);
    }
}

// block-local inclusive scan of in-degree counts -> exclusive prefix in row_ptr
__global__ void k_scan1(int n) {
    __shared__ int sh[1024];
    int t = threadIdx.x;
    int i = blockIdx.x * 1024 + t;
    int v = (i < n) ? g_cnt_in[i] : 0;
    sh[t] = v;
    __syncthreads();
    #pragma unroll
    for (int off = 1; off < 1024; off <<= 1) {
        int x = (t >= off) ? sh[t - off] : 0;
        __syncthreads();
        sh[t] += x;
        __syncthreads();
    }
    int incl = sh[t];
    if (i < n) g_row_ptr[i] = incl - v;          // block-local exclusive
    if (t == 1023) g_blk[blockIdx.x] = incl;     // block total
}

__global__ void k_scan2(int nb, int n) {
    if (threadIdx.x == 0 && blockIdx.x == 0) {
        int run = 0;
        for (int b = 0; b < nb; b++) { int x = g_blk[b]; g_blk[b] = run; run += x; }
        g_row_ptr[n] = run;
    }
}

__global__ void k_scan3(int n) {
    int i = blockIdx.x * blockDim.x + threadIdx.x;
    if (i < n) g_row_ptr[i] += g_blk[i >> 10];
}

__global__ void k_scatter(const int* __restrict__ src,
                          const int* __restrict__ dst, int e, int n) {
    int i = blockIdx.x * blockDim.x + threadIdx.x;
    if (i < e) {
        int d = clamp_idx(dst[i], n);
        int pos = g_row_ptr[d] + atomicAdd(&g_cursor[d], 1);
        if (pos < EE) g_col[pos] = clamp_idx(src[i], n);
    }
}

__global__ void k_norms(int n) {
    int i = blockIdx.x * blockDim.x + threadIdx.x;
    if (i < n) {
        int co = g_cnt_out[i]; if (co < 1) co = 1;
        int ci = g_cnt_in[i];  if (ci < 1) ci = 1;
        g_iso[i] = rsqrtf((float)co);
        g_isi[i] = rsqrtf((float)ci);
    }
}

// ---------------- layer kernels ---------------------------------------------
// hs[node] = input[node] * iso[node]
__global__ void k_scale(const float4* __restrict__ in, int use_h1, int total4) {
    int i = blockIdx.x * blockDim.x + threadIdx.x;
    if (i < total4) {
        float4 a = use_h1 ? g_h1[i] : in[i];
        float s = g_iso[i >> 5];
        g_hs[i] = make_float4(a.x * s, a.y * s, a.z * s, a.w * s);
    }
}

// agg[dst] = isi[dst] * sum_{src in row(dst)} hs[src]  — one warp per dst node
__global__ void k_spmm(int n) {
    int t = threadIdx.x;
    int lane = t & 31;
    int w = t >> 5;
    int node = blockIdx.x * 4 + w;
    if (node >= n) return;
    int beg = g_row_ptr[node];
    int cnt = g_cnt_in[node];
    float4 acc = make_float4(0.f, 0.f, 0.f, 0.f);
    #pragma unroll 4
    for (int e = 0; e < cnt; e++) {
        int s = g_col[beg + e];
        float4 v = g_hs[s * NV4 + lane];
        acc.x += v.x; acc.y += v.y; acc.z += v.z; acc.w += v.w;
    }
    float si = g_isi[node];
    acc.x *= si; acc.y *= si; acc.z *= si; acc.w *= si;
    g_agg[node * NV4 + lane] = acc;
}

// out[node] = relu(LN(agg[node] @ W + b))  — one warp per node, 4 cols/thread
__global__ void k_gemm_ln_relu(const float* __restrict__ Wp,
                               const float* __restrict__ bp,
                               const float* __restrict__ gp,
                               const float* __restrict__ bep,
                               float4* __restrict__ out, int to_h1, int n) {
    __shared__ float4 s4[4][NV4];
    int t = threadIdx.x;
    int lane = t & 31;
    int w = t >> 5;
    int node = blockIdx.x * 4 + w;
    if (node >= n) return;

    s4[w][lane] = g_agg[node * NV4 + lane];
    __syncwarp();
    const float* srow = (const float*)s4[w];

    float4 acc = ((const float4*)bp)[lane];
    const float4* W4 = (const float4*)Wp;
    #pragma unroll 8
    for (int k = 0; k < DD; k++) {
        float sk = srow[k];
        float4 ww = W4[k * NV4 + lane];
        acc.x = fmaf(sk, ww.x, acc.x);
        acc.y = fmaf(sk, ww.y, acc.y);
        acc.z = fmaf(sk, ww.z, acc.z);
        acc.w = fmaf(sk, ww.w, acc.w);
    }

    // warp-level LayerNorm over the 128 outputs
    float sum = acc.x + acc.y + acc.z + acc.w;
    float sq  = acc.x * acc.x + acc.y * acc.y + acc.z * acc.z + acc.w * acc.w;
    #pragma unroll
    for (int off = 16; off > 0; off >>= 1) {
        sum += __shfl_xor_sync(0xffffffffu, sum, off);
        sq  += __shfl_xor_sync(0xffffffffu, sq,  off);
    }
    float mu  = sum * (1.0f / DD);
    float var = sq * (1.0f / DD) - mu * mu;
    float r   = rsqrtf(var + LN_EPS);

    float4 gg = ((const float4*)gp)[lane];
    float4 bb = ((const float4*)bep)[lane];
    float4 o4;
    o4.x = fmaxf(0.f, (acc.x - mu) * r * gg.x + bb.x);
    o4.y = fmaxf(0.f, (acc.y - mu) * r * gg.y + bb.y);
    o4.z = fmaxf(0.f, (acc.z - mu) * r * gg.z + bb.z);
    o4.w = fmaxf(0.f, (acc.w - mu) * r * gg.w + bb.w);

    if (to_h1) g_h1[node * NV4 + lane] = o4;
    else       out [node * NV4 + lane] = o4;
}

// ---------------- host launch ------------------------------------------------
extern "C" void kernel_launch(void* const* d_in, const int* in_sizes, int n_in,
                              void* d_out, int out_size) {
    const float* feat = (const float*)d_in[0];
    const int*   src  = (const int*)d_in[1];   // JAX default: int64 request -> int32
    const int*   dst  = (const int*)d_in[2];
    const float* W1  = (const float*)d_in[3];
    const float* b1  = (const float*)d_in[4];
    const float* g1  = (const float*)d_in[5];
    const float* be1 = (const float*)d_in[6];
    const float* W2  = (const float*)d_in[7];
    const float* b2  = (const float*)d_in[8];
    const float* g2  = (const float*)d_in[9];
    const float* be2 = (const float*)d_in[10];

    int n = in_sizes[0] / DD;   // 50000
    int e = in_sizes[1];        // 800000
    int total4 = n * NV4;

    int gbN  = (n + 255) / 256;
    int gbE  = (e + 255) / 256;
    int nbSc = (n + 1023) / 1024;
    int gb4  = (total4 + 255) / 256;
    int gbW  = (n + 3) / 4;     // 4 warps (nodes) per block

    // graph prep
    k_zero   <<<gbN, 256>>>(n);
    k_degree <<<gbE, 256>>>(src, dst, e, n);
    k_scan1  <<<nbSc, 1024>>>(n);
    k_scan2  <<<1, 32>>>(nbSc, n);
    k_scan3  <<<gbN, 256>>>(n);
    k_scatter<<<gbE, 256>>>(src, dst, e, n);
    k_norms  <<<gbN, 256>>>(n);

    // layer 1
    k_scale       <<<gb4, 256>>>((const float4*)feat, 0, total4);
    k_spmm        <<<gbW, 128>>>(n);
    k_gemm_ln_relu<<<gbW, 128>>>(W1, b1, g1, be1, (float4*)d_out, 1, n);

    // layer 2
    k_scale       <<<gb4, 256>>>((const float4*)feat, 1, total4);
    k_spmm        <<<gbW, 128>>>(n);
    k_gemm_ln_relu<<<gbW, 128>>>(W2, b2, g2, be2, (float4*)d_out, 0, n);
}